// round 15
// baseline (speedup 1.0000x reference)
#include <cuda_runtime.h>
#include <cuda_bf16.h>
#include <cstdint>
#include <cfloat>

#define NB      4096
#define NDIM    128
#define GT      128
#define NGT     (NB / GT)                 // 32
#define NGPAIRS (NGT * (NGT + 1) / 2)     // 528
#define NCLASS  100
#define MAXMEM  64

typedef unsigned long long u64;

// ---------------- device scratch (static, no allocation) --------------------
__device__ __nv_bfloat16 g_embH[NB * NDIM];
__device__ __nv_bfloat16 g_embL[NB * NDIM];
__device__ float g_sqnorm[NB];
__device__ u64   g_best[NB];
__device__ int   g_posidx[NB];
__device__ float g_loss[NB];
__device__ float g_cnt[NB];
__device__ int   g_ccnt[NCLASS];
__device__ int   g_members[NCLASS * MAXMEM];

// ---------------- mma.sync m16n8k16 bf16 (sm_80+, compiles on compute_100) --
__device__ __forceinline__ void mma_bf16(float* c, const uint32_t* a,
                                         const uint32_t* b) {
    asm volatile(
        "mma.sync.aligned.m16n8k16.row.col.f32.bf16.bf16.f32 "
        "{%0,%1,%2,%3}, {%4,%5,%6,%7}, {%8,%9}, {%0,%1,%2,%3};"
        : "+f"(c[0]), "+f"(c[1]), "+f"(c[2]), "+f"(c[3])
        : "r"(a[0]), "r"(a[1]), "r"(a[2]), "r"(a[3]),
          "r"(b[0]), "r"(b[1]));
}

// ---------------- threefry2x32 ----------------------------------------------
__host__ __device__ __forceinline__ void tf2x32(uint32_t k0, uint32_t k1,
                                                uint32_t c0, uint32_t c1,
                                                uint32_t& o0, uint32_t& o1) {
    const uint32_t ks2 = k0 ^ k1 ^ 0x1BD11BDAu;
    uint32_t x0 = c0 + k0;
    uint32_t x1 = c1 + k1;
#define TFR(r) { x0 += x1; x1 = (x1 << r) | (x1 >> (32 - r)); x1 ^= x0; }
    TFR(13) TFR(15) TFR(26) TFR(6)   x0 += k1;  x1 += ks2 + 1u;
    TFR(17) TFR(29) TFR(16) TFR(24)  x0 += ks2; x1 += k0  + 2u;
    TFR(13) TFR(15) TFR(26) TFR(6)   x0 += k0;  x1 += k1  + 3u;
    TFR(17) TFR(29) TFR(16) TFR(24)  x0 += k1;  x1 += ks2 + 4u;
    TFR(13) TFR(15) TFR(26) TFR(6)   x0 += ks2; x1 += k0  + 5u;
#undef TFR
    o0 = x0; o1 = x1;
}
__device__ __forceinline__ uint32_t jax_bits32(uint32_t k0, uint32_t k1, uint32_t n) {
    uint32_t o0, o1;
    tf2x32(k0, k1, 0u, n, o0, o1);
    return o0 ^ o1;
}
__device__ __forceinline__ float jax_gumbel(uint32_t bits) {
    float f = __uint_as_float((bits >> 9) | 0x3f800000u) - 1.0f;
    float u = fmaxf(f, 1.17549435e-38f);
    float nl = -logf(u);               // accurate: u->1 tail decides winners
    return -__logf(nl);
}
__device__ __forceinline__ u64 pack_vi(float v, int idx) {
    uint32_t s = __float_as_uint(v);
    s = (s & 0x80000000u) ? ~s : (s | 0x80000000u);
    return ((u64)s << 32) | (uint32_t)(0xFFFFFFFFu - (uint32_t)idx);
}

// ---------------- prep: fp32 -> bf16 hi/lo split -----------------------------
__global__ void convert_k(const float* __restrict__ emb) {
    int idx = blockIdx.x * blockDim.x + threadIdx.x;   // float4 units
    float4 v = ((const float4*)emb)[idx];
    __nv_bfloat16 h0 = __float2bfloat16(v.x), h1 = __float2bfloat16(v.y);
    __nv_bfloat16 h2 = __float2bfloat16(v.z), h3 = __float2bfloat16(v.w);
    __nv_bfloat16 l0 = __float2bfloat16(v.x - __bfloat162float(h0));
    __nv_bfloat16 l1 = __float2bfloat16(v.y - __bfloat162float(h1));
    __nv_bfloat16 l2 = __float2bfloat16(v.z - __bfloat162float(h2));
    __nv_bfloat16 l3 = __float2bfloat16(v.w - __bfloat162float(h3));
    __nv_bfloat162 ph0; ph0.x = h0; ph0.y = h1;
    __nv_bfloat162 ph1; ph1.x = h2; ph1.y = h3;
    __nv_bfloat162 pl0; pl0.x = l0; pl0.y = l1;
    __nv_bfloat162 pl1; pl1.x = l2; pl1.y = l3;
    ((__nv_bfloat162*)g_embH)[idx * 2]     = ph0;
    ((__nv_bfloat162*)g_embH)[idx * 2 + 1] = ph1;
    ((__nv_bfloat162*)g_embL)[idx * 2]     = pl0;
    ((__nv_bfloat162*)g_embL)[idx * 2 + 1] = pl1;
}

__global__ void norm_k(const float* __restrict__ emb) {
    int gid = blockIdx.x * blockDim.x + threadIdx.x;
    if (gid < NCLASS) g_ccnt[gid] = 0;
    int w = gid >> 5;
    int lane = threadIdx.x & 31;
    if (w >= NB) return;
    float4 v = *(const float4*)(emb + w * NDIM + lane * 4);
    float s = v.x * v.x + v.y * v.y + v.z * v.z + v.w * v.w;
#pragma unroll
    for (int o = 16; o; o >>= 1) s += __shfl_xor_sync(0xFFFFFFFFu, s, o);
    if (lane == 0) { g_sqnorm[w] = s; g_best[w] = 0ull; }
}

__global__ void bin_k(const int* __restrict__ labels) {
    int i = blockIdx.x * blockDim.x + threadIdx.x;
    if (i >= NB) return;
    int c = labels[i];
    int s = atomicAdd(&g_ccnt[c], 1);
    if (s < MAXMEM) g_members[c * MAXMEM + s] = i;
}

// ---------------- fused: tensor-core Gram + logits + gumbel + argmax --------
// Fragment map (m16n8k16, row.col), verified rel_err=0 in rounds 13/14.
// acc[s][q]: row = mrow + (q>=2)*8, col = col0 + s*8 + tig*2 + (q&1)
__global__ void __launch_bounds__(256, 2)
fused_k(const int* __restrict__ labels, uint32_t kn0, uint32_t kn1) {
    __shared__ uint32_t sAH[GT * 8], sAL[GT * 8];   // 128 rows x 16 bf16 chunk
    __shared__ uint32_t sBH[GT * 8], sBL[GT * 8];
    __shared__ int   labA[GT], labB[GT];
    __shared__ float sqA[GT], sqB[GT];
    __shared__ u64   redA[GT], redB[GT];

    const int tid = threadIdx.x;
    const int w = tid >> 5;
    const int lane = tid & 31;
    const int g = lane >> 2, tig = lane & 3;

    // decode triangular pair over 128-tiles
    int bid = blockIdx.x;
    int I = (int)((2.0f * NGT + 1.0f
                   - sqrtf((2.0f * NGT + 1.0f) * (2.0f * NGT + 1.0f)
                           - 8.0f * (float)bid)) * 0.5f);
    while (I * (2 * NGT + 1 - I) / 2 > bid) I--;
    while ((I + 1) * (2 * NGT - I) / 2 <= bid) I++;
    const int J = I + (bid - I * (2 * NGT + 1 - I) / 2);
    const int row0 = I * GT;
    const int col0 = J * GT;
    const bool diag = (I == J);

    if (tid < GT) {
        labA[tid] = labels[row0 + tid]; sqA[tid] = g_sqnorm[row0 + tid];
        redA[tid] = 0ull;
    } else {
        int q = tid - GT;
        labB[q] = labels[col0 + q]; sqB[q] = g_sqnorm[col0 + q];
        redB[q] = 0ull;
    }

    const uint32_t* H = (const uint32_t*)g_embH;   // 64 words per row
    const uint32_t* L = (const uint32_t*)g_embL;
    const int arow = w * 16 + g;                   // local A row
    const int mrow = row0 + arow;                  // global A row

    float acc[16][4];
#pragma unroll
    for (int s = 0; s < 16; s++)
#pragma unroll
        for (int q = 0; q < 4; q++) acc[s][q] = 0.f;

    for (int kc = 0; kc < 8; kc++) {
        const int wb = kc * 8;
        __syncthreads();
        for (int idx = tid; idx < GT * 8; idx += 256) {
            int row = idx >> 3, wc = idx & 7;
            sAH[idx] = H[(size_t)(row0 + row) * 64 + wb + wc];
            sAL[idx] = L[(size_t)(row0 + row) * 64 + wb + wc];
            sBH[idx] = H[(size_t)(col0 + row) * 64 + wb + wc];
            sBL[idx] = L[(size_t)(col0 + row) * 64 + wb + wc];
        }
        __syncthreads();

        uint32_t ah[4], al[4];
        ah[0] = sAH[arow * 8 + tig];         ah[1] = sAH[(arow + 8) * 8 + tig];
        ah[2] = sAH[arow * 8 + tig + 4];     ah[3] = sAH[(arow + 8) * 8 + tig + 4];
        al[0] = sAL[arow * 8 + tig];         al[1] = sAL[(arow + 8) * 8 + tig];
        al[2] = sAL[arow * 8 + tig + 4];     al[3] = sAL[(arow + 8) * 8 + tig + 4];

#pragma unroll
        for (int s = 0; s < 16; s++) {
            const int brow = s * 8 + g;
            uint32_t bh[2] = {sBH[brow * 8 + tig], sBH[brow * 8 + tig + 4]};
            uint32_t bl[2] = {sBL[brow * 8 + tig], sBL[brow * 8 + tig + 4]};
            mma_bf16(acc[s], ah, bh);   // hi*hi
            mma_bf16(acc[s], ah, bl);   // hi*lo
            mma_bf16(acc[s], al, bh);   // lo*hi  (lo*lo dropped: <=4e-6)
        }
    }
    __syncthreads();   // all inits + tiles done; regs hold the 128x128 dots

    // ---------------- epilogue on registers ----------------
    const int labr0 = labA[arow],     labr1 = labA[arow + 8];
    const float sqr0 = sqA[arow],     sqr1 = sqA[arow + 8];
    u64 bestR0 = 0ull, bestR1 = 0ull;

#pragma unroll
    for (int s = 0; s < 16; s++) {
#pragma unroll
        for (int h = 0; h < 2; h++) {
            const int cl = s * 8 + tig * 2 + h;
            const int j  = col0 + cl;
            const int labj = labB[cl];
            const float sqj = sqB[cl];
            u64 bestC = 0ull;
#pragma unroll
            for (int rs = 0; rs < 2; rs++) {
                const int labr = rs ? labr1 : labr0;
                if (labr == labj) continue;       // same-label -> -inf logit
                const float dot = acc[s][rs * 2 + h];
                const int i = mrow + rs * 8;
                float d2 = ((rs ? sqr1 : sqr0) + sqj) - 2.0f * dot;
                d2 = fmaxf(d2, 0.25f);            // == clip d at 0.5
                d2 = fminf(d2, 3.999f);           // guard log(<=0)
                float lq = -63.0f * __logf(d2)
                           - 62.5f * __logf(fmaf(-0.25f, d2, 1.0f));
                {   // orientation 1: anchor i, candidate j
                    uint32_t bits = jax_bits32(kn0, kn1, (uint32_t)(i * NB + j));
                    u64 p = pack_vi(lq + jax_gumbel(bits), j);
                    if (rs) { if (p > bestR1) bestR1 = p; }
                    else    { if (p > bestR0) bestR0 = p; }
                }
                if (!diag) {  // orientation 2: anchor j, candidate i
                    uint32_t bits = jax_bits32(kn0, kn1, (uint32_t)(j * NB + i));
                    u64 p = pack_vi(lq + jax_gumbel(bits), i);
                    if (p > bestC) bestC = p;
                }
            }
            if (bestC) atomicMax(&redB[cl], bestC);
        }
    }
    if (bestR0) atomicMax(&redA[arow], bestR0);
    if (bestR1) atomicMax(&redA[arow + 8], bestR1);
    __syncthreads();

    if (tid < GT) {
        if (redA[tid]) atomicMax(&g_best[row0 + tid], redA[tid]);
    } else if (!diag) {
        int q = tid - GT;
        if (redB[q]) atomicMax(&g_best[col0 + q], redB[q]);
    }
}

// ---------------- positives: warp-per-anchor over class member list ---------
__global__ void pos_sample_k(const int* __restrict__ labels,
                             uint32_t kp0, uint32_t kp1) {
    const int t = threadIdx.x;
    const int anchor = (blockIdx.x * 256 + t) >> 5;
    const int lane = t & 31;
    const int li = labels[anchor];
    const int cnt = min(g_ccnt[li], MAXMEM);
    u64 best = 0ull;
    for (int s = lane; s < cnt; s += 32) {
        int j = g_members[li * MAXMEM + s];
        if (j != anchor) {
            uint32_t bits = jax_bits32(kp0, kp1, (uint32_t)(anchor * NB + j));
            u64 p = pack_vi(jax_gumbel(bits), j);
            if (p > best) best = p;
        }
    }
#pragma unroll
    for (int o = 16; o; o >>= 1) {
        u64 q = __shfl_xor_sync(0xFFFFFFFFu, best, o);
        if (q > best) best = q;
    }
    if (lane == 0)
        g_posidx[anchor] = (int)(0xFFFFFFFFu - (uint32_t)best);
}

// ---------------- finalize + reduce ------------------------------------------
__global__ void finalize_k(const float* __restrict__ emb,
                           const int* __restrict__ labels,
                           const float* __restrict__ beta) {
    int w = (blockIdx.x * blockDim.x + threadIdx.x) >> 5;
    int lane = threadIdx.x & 31;
    if (w >= NB) return;
    int pi = g_posidx[w];
    int ni = (int)(0xFFFFFFFFu - (uint32_t)g_best[w]);
    float4 a = *(const float4*)(emb + w * NDIM + lane * 4);
    float4 p = *(const float4*)(emb + pi * NDIM + lane * 4);
    float4 n = *(const float4*)(emb + ni * NDIM + lane * 4);
    float dx, sap, san;
    dx = a.x - p.x; sap = dx * dx; dx = a.y - p.y; sap += dx * dx;
    dx = a.z - p.z; sap += dx * dx; dx = a.w - p.w; sap += dx * dx;
    dx = a.x - n.x; san = dx * dx; dx = a.y - n.y; san += dx * dx;
    dx = a.z - n.z; san += dx * dx; dx = a.w - n.w; san += dx * dx;
#pragma unroll
    for (int o = 16; o; o >>= 1) {
        sap += __shfl_xor_sync(0xFFFFFFFFu, sap, o);
        san += __shfl_xor_sync(0xFFFFFFFFu, san, o);
    }
    if (lane == 0) {
        float d_ap = sqrtf(sap + 1e-8f);
        float d_an = sqrtf(san + 1e-8f);
        float ba = beta[labels[w]];
        float pl = fmaxf(d_ap - ba + 0.2f, 0.0f);
        float nl = fmaxf(ba - d_an + 0.2f, 0.0f);
        g_loss[w] = pl + nl;
        g_cnt[w]  = (pl > 0.0f ? 1.0f : 0.0f) + (nl > 0.0f ? 1.0f : 0.0f);
    }
}

__global__ void reduce_k(float* __restrict__ out) {
    __shared__ float st[256], sc[256];
    int t = threadIdx.x;
    float s = 0.f, c = 0.f;
    for (int i = t; i < NB; i += 256) { s += g_loss[i]; c += g_cnt[i]; }
    st[t] = s; sc[t] = c;
    __syncthreads();
    for (int o = 128; o; o >>= 1) {
        if (t < o) { st[t] += st[t + o]; sc[t] += sc[t + o]; }
        __syncthreads();
    }
    if (t == 0) out[0] = (sc[0] == 0.0f) ? st[0] : st[0] / sc[0];
}

// ---------------- host -------------------------------------------------------
extern "C" void kernel_launch(void* const* d_in, const int* in_sizes, int n_in,
                              void* d_out, int out_size) {
    const float* emb    = (const float*)d_in[0];
    const int*   labels = (const int*)d_in[1];
    const float* beta   = (const float*)d_in[2];
    float* out = (float*)d_out;

    uint32_t kn0, kn1, kp0, kp1;
    tf2x32(0u, 42u, 0u, 0u, kn0, kn1);   // foldlike split: k_neg
    tf2x32(0u, 42u, 0u, 1u, kp0, kp1);   // k_pos

    convert_k<<<NB * NDIM / 4 / 256, 256>>>(emb);
    norm_k<<<NB * 32 / 256, 256>>>(emb);
    bin_k<<<NB / 256, 256>>>(labels);
    fused_k<<<NGPAIRS, 256>>>(labels, kn0, kn1);
    pos_sample_k<<<NB / 8, 256>>>(labels, kp0, kp1);
    finalize_k<<<NB * 32 / 256, 256>>>(emb, labels, beta);
    reduce_k<<<1, 256>>>(out);
}

// round 16
// speedup vs baseline: 1.0619x; 1.0619x over previous
#include <cuda_runtime.h>
#include <cuda_bf16.h>
#include <cstdint>
#include <cfloat>

#define NB      4096
#define NDIM    128
// GEMM tiles (tensor core, mma.sync)
#define GT      128
#define NGT     (NB / GT)                 // 32
#define NGPAIRS (NGT * (NGT + 1) / 2)     // 528
// sampling tiles
#define BT      64
#define NRT     (NB / BT)                 // 64
#define NPAIRS  (NRT * (NRT + 1) / 2)     // 2080
#define NTHREADS 256
#define NCLASS  100
#define MAXMEM  64

typedef unsigned long long u64;

// ---------------- device scratch (static, no allocation) --------------------
__device__ __nv_bfloat16 g_embH[NB * NDIM];
__device__ __nv_bfloat16 g_embL[NB * NDIM];
__device__ float g_dot[(size_t)NB * NB];     // 64MB; upper 128-tiles written
__device__ float g_sqnorm[NB];
__device__ u64   g_best[NB];
__device__ int   g_posidx[NB];
__device__ float g_loss[NB];
__device__ float g_cnt[NB];
__device__ int   g_ccnt[NCLASS];
__device__ int   g_members[NCLASS * MAXMEM];

// ---------------- mma.sync m16n8k16 bf16 (sm_80+, compiles on compute_100) --
__device__ __forceinline__ void mma_bf16(float* c, const uint32_t* a,
                                         const uint32_t* b) {
    asm volatile(
        "mma.sync.aligned.m16n8k16.row.col.f32.bf16.bf16.f32 "
        "{%0,%1,%2,%3}, {%4,%5,%6,%7}, {%8,%9}, {%0,%1,%2,%3};"
        : "+f"(c[0]), "+f"(c[1]), "+f"(c[2]), "+f"(c[3])
        : "r"(a[0]), "r"(a[1]), "r"(a[2]), "r"(a[3]),
          "r"(b[0]), "r"(b[1]));
}

// ---------------- threefry2x32 ----------------------------------------------
__host__ __device__ __forceinline__ void tf2x32(uint32_t k0, uint32_t k1,
                                                uint32_t c0, uint32_t c1,
                                                uint32_t& o0, uint32_t& o1) {
    const uint32_t ks2 = k0 ^ k1 ^ 0x1BD11BDAu;
    uint32_t x0 = c0 + k0;
    uint32_t x1 = c1 + k1;
#define TFR(r) { x0 += x1; x1 = (x1 << r) | (x1 >> (32 - r)); x1 ^= x0; }
    TFR(13) TFR(15) TFR(26) TFR(6)   x0 += k1;  x1 += ks2 + 1u;
    TFR(17) TFR(29) TFR(16) TFR(24)  x0 += ks2; x1 += k0  + 2u;
    TFR(13) TFR(15) TFR(26) TFR(6)   x0 += k0;  x1 += k1  + 3u;
    TFR(17) TFR(29) TFR(16) TFR(24)  x0 += k1;  x1 += ks2 + 4u;
    TFR(13) TFR(15) TFR(26) TFR(6)   x0 += ks2; x1 += k0  + 5u;
#undef TFR
    o0 = x0; o1 = x1;
}
__device__ __forceinline__ uint32_t jax_bits32(uint32_t k0, uint32_t k1, uint32_t n) {
    uint32_t o0, o1;
    tf2x32(k0, k1, 0u, n, o0, o1);
    return o0 ^ o1;
}
__device__ __forceinline__ float jax_gumbel(uint32_t bits) {
    float f = __uint_as_float((bits >> 9) | 0x3f800000u) - 1.0f;
    float u = fmaxf(f, 1.17549435e-38f);
    float nl = -logf(u);               // accurate: u->1 tail decides winners
    return -__logf(nl);
}
__device__ __forceinline__ u64 pack_vi(float v, int idx) {
    uint32_t s = __float_as_uint(v);
    s = (s & 0x80000000u) ? ~s : (s | 0x80000000u);
    return ((u64)s << 32) | (uint32_t)(0xFFFFFFFFu - (uint32_t)idx);
}

// ---------------- prep: fp32 -> bf16 hi/lo split -----------------------------
__global__ void convert_k(const float* __restrict__ emb) {
    int idx = blockIdx.x * blockDim.x + threadIdx.x;   // float4 units
    float4 v = ((const float4*)emb)[idx];
    __nv_bfloat16 h0 = __float2bfloat16(v.x), h1 = __float2bfloat16(v.y);
    __nv_bfloat16 h2 = __float2bfloat16(v.z), h3 = __float2bfloat16(v.w);
    __nv_bfloat16 l0 = __float2bfloat16(v.x - __bfloat162float(h0));
    __nv_bfloat16 l1 = __float2bfloat16(v.y - __bfloat162float(h1));
    __nv_bfloat16 l2 = __float2bfloat16(v.z - __bfloat162float(h2));
    __nv_bfloat16 l3 = __float2bfloat16(v.w - __bfloat162float(h3));
    __nv_bfloat162 ph0; ph0.x = h0; ph0.y = h1;
    __nv_bfloat162 ph1; ph1.x = h2; ph1.y = h3;
    __nv_bfloat162 pl0; pl0.x = l0; pl0.y = l1;
    __nv_bfloat162 pl1; pl1.x = l2; pl1.y = l3;
    ((__nv_bfloat162*)g_embH)[idx * 2]     = ph0;
    ((__nv_bfloat162*)g_embH)[idx * 2 + 1] = ph1;
    ((__nv_bfloat162*)g_embL)[idx * 2]     = pl0;
    ((__nv_bfloat162*)g_embL)[idx * 2 + 1] = pl1;
}

__global__ void norm_k(const float* __restrict__ emb) {
    int gid = blockIdx.x * blockDim.x + threadIdx.x;
    if (gid < NCLASS) g_ccnt[gid] = 0;
    int w = gid >> 5;
    int lane = threadIdx.x & 31;
    if (w >= NB) return;
    float4 v = *(const float4*)(emb + w * NDIM + lane * 4);
    float s = v.x * v.x + v.y * v.y + v.z * v.z + v.w * v.w;
#pragma unroll
    for (int o = 16; o; o >>= 1) s += __shfl_xor_sync(0xFFFFFFFFu, s, o);
    if (lane == 0) { g_sqnorm[w] = s; g_best[w] = 0ull; }
}

__global__ void bin_k(const int* __restrict__ labels) {
    int i = blockIdx.x * blockDim.x + threadIdx.x;
    if (i >= NB) return;
    int c = labels[i];
    int s = atomicAdd(&g_ccnt[c], 1);
    if (s < MAXMEM) g_members[c * MAXMEM + s] = i;
}

// ---------------- tensor-core Gram: smem-staged (32-wide k-chunks) ----------
// Fragment map (m16n8k16, row.col), verified rel_err=0 in rounds 13-15.
__global__ void __launch_bounds__(256, 2)
gemm_k() {
    __shared__ uint32_t sAH[GT * 16], sAL[GT * 16];   // 128 rows x 32 bf16
    __shared__ uint32_t sBH[GT * 16], sBL[GT * 16];

    const int tid = threadIdx.x;
    const int w = tid >> 5;
    const int lane = tid & 31;
    const int g = lane >> 2, tig = lane & 3;

    // decode triangular pair over 128-tiles
    int bid = blockIdx.x;
    int I = (int)((2.0f * NGT + 1.0f
                   - sqrtf((2.0f * NGT + 1.0f) * (2.0f * NGT + 1.0f)
                           - 8.0f * (float)bid)) * 0.5f);
    while (I * (2 * NGT + 1 - I) / 2 > bid) I--;
    while ((I + 1) * (2 * NGT - I) / 2 <= bid) I++;
    const int J = I + (bid - I * (2 * NGT + 1 - I) / 2);
    const int row0 = I * GT;
    const int col0 = J * GT;

    const uint32_t* H = (const uint32_t*)g_embH;   // 64 words per row
    const uint32_t* L = (const uint32_t*)g_embL;
    const int arow = w * 16 + g;                   // local A row

    float acc[16][4];
#pragma unroll
    for (int s = 0; s < 16; s++)
#pragma unroll
        for (int q = 0; q < 4; q++) acc[s][q] = 0.f;

    for (int kc = 0; kc < 4; kc++) {               // 32-bf16 chunks
        const int wb = kc * 16;
        __syncthreads();
        for (int idx = tid; idx < GT * 16; idx += 256) {
            int row = idx >> 4, wc = idx & 15;
            sAH[idx] = H[(size_t)(row0 + row) * 64 + wb + wc];
            sAL[idx] = L[(size_t)(row0 + row) * 64 + wb + wc];
            sBH[idx] = H[(size_t)(col0 + row) * 64 + wb + wc];
            sBL[idx] = L[(size_t)(col0 + row) * 64 + wb + wc];
        }
        __syncthreads();

        uint32_t ah[2][4], al[2][4];
#pragma unroll
        for (int kb = 0; kb < 2; kb++) {
            int o = kb * 8;
            ah[kb][0] = sAH[arow * 16 + o + tig];
            ah[kb][1] = sAH[(arow + 8) * 16 + o + tig];
            ah[kb][2] = sAH[arow * 16 + o + tig + 4];
            ah[kb][3] = sAH[(arow + 8) * 16 + o + tig + 4];
            al[kb][0] = sAL[arow * 16 + o + tig];
            al[kb][1] = sAL[(arow + 8) * 16 + o + tig];
            al[kb][2] = sAL[arow * 16 + o + tig + 4];
            al[kb][3] = sAL[(arow + 8) * 16 + o + tig + 4];
        }

#pragma unroll
        for (int s = 0; s < 16; s++) {
            const int brow = s * 8 + g;
#pragma unroll
            for (int kb = 0; kb < 2; kb++) {       // ascending k order preserved
                int o = kb * 8;
                uint32_t bh[2] = {sBH[brow * 16 + o + tig],
                                  sBH[brow * 16 + o + tig + 4]};
                uint32_t bl[2] = {sBL[brow * 16 + o + tig],
                                  sBL[brow * 16 + o + tig + 4]};
                mma_bf16(acc[s], ah[kb], bh);   // hi*hi
                mma_bf16(acc[s], ah[kb], bl);   // hi*lo
                mma_bf16(acc[s], al[kb], bh);   // lo*hi (lo*lo dropped)
            }
        }
    }

    const int mrow = row0 + arow;
#pragma unroll
    for (int s = 0; s < 16; s++) {
        const int col = col0 + s * 8 + tig * 2;
        float2 lo; lo.x = acc[s][0]; lo.y = acc[s][1];
        float2 hi; hi.x = acc[s][2]; hi.y = acc[s][3];
        *(float2*)&g_dot[(size_t)mrow * NB + col] = lo;
        *(float2*)&g_dot[(size_t)(mrow + 8) * NB + col] = hi;
    }
}

// ---------------- negatives: epilogue-only over precomputed dots ------------
__global__ void __launch_bounds__(NTHREADS, 5)
neg_sample_k(const int* __restrict__ labels, uint32_t kn0, uint32_t kn1) {
    __shared__ int labA[BT], labB[BT];
    __shared__ float sqA[BT], sqB[BT];
    __shared__ u64 redA[BT], redB[BT];

    const int tid = threadIdx.x;
    const int tr = tid >> 4;
    const int tc = tid & 15;

    int bid = blockIdx.x;
    int I = (int)((2.0f * NRT + 1.0f
                   - sqrtf((2.0f * NRT + 1.0f) * (2.0f * NRT + 1.0f)
                           - 8.0f * (float)bid)) * 0.5f);
    while (I * (2 * NRT + 1 - I) / 2 > bid) I--;
    while ((I + 1) * (2 * NRT - I) / 2 <= bid) I++;
    const int J = I + (bid - I * (2 * NRT + 1 - I) / 2);
    const int row0 = I * BT;
    const int col0 = J * BT;
    const bool diag = (I == J);

    if (tid < BT) {
        labA[tid] = labels[row0 + tid]; sqA[tid] = g_sqnorm[row0 + tid];
        redA[tid] = 0ull;
    } else if (tid < 2 * BT) {
        int q = tid - BT;
        labB[q] = labels[col0 + q]; sqB[q] = g_sqnorm[col0 + q];
        redB[q] = 0ull;
    }
    __syncthreads();

    float acc[4][4];
#pragma unroll
    for (int r = 0; r < 4; r++) {
        float4 v = *(const float4*)&g_dot[(size_t)(row0 + tr * 4 + r) * NB
                                          + col0 + tc * 4];
        acc[r][0] = v.x; acc[r][1] = v.y; acc[r][2] = v.z; acc[r][3] = v.w;
    }

    float sqr[4]; int labr[4];
#pragma unroll
    for (int r = 0; r < 4; r++) {
        sqr[r]  = sqA[tr * 4 + r];
        labr[r] = labA[tr * 4 + r];
    }

    u64 best1[4] = {0ull, 0ull, 0ull, 0ull};
    u64 best2[4] = {0ull, 0ull, 0ull, 0ull};

#pragma unroll
    for (int cc = 0; cc < 4; cc++) {
        const int cl = tc * 4 + cc;
        const int j  = col0 + cl;
        const int labj = labB[cl];
        const float sqj = sqB[cl];
#pragma unroll
        for (int r = 0; r < 4; r++) {
            if (labr[r] == labj) continue;      // same-label -> -inf logit
            const int i = row0 + tr * 4 + r;
            float d2 = (sqr[r] + sqj) - 2.0f * acc[r][cc];
            d2 = fmaxf(d2, 0.25f);              // == clip d at 0.5
            d2 = fminf(d2, 3.999f);             // guard log(<=0)
            float lq = -63.0f * __logf(d2)
                       - 62.5f * __logf(fmaf(-0.25f, d2, 1.0f));
            {   // orientation 1: anchor i, candidate j
                uint32_t bits = jax_bits32(kn0, kn1, (uint32_t)(i * NB + j));
                u64 p = pack_vi(lq + jax_gumbel(bits), j);
                if (p > best1[r]) best1[r] = p;
            }
            if (!diag) {  // orientation 2: anchor j, candidate i
                uint32_t bits = jax_bits32(kn0, kn1, (uint32_t)(j * NB + i));
                u64 p = pack_vi(lq + jax_gumbel(bits), i);
                if (p > best2[cc]) best2[cc] = p;
            }
        }
    }

#pragma unroll
    for (int r = 0; r < 4; r++)
        if (best1[r]) atomicMax(&redA[tr * 4 + r], best1[r]);
    if (!diag) {
#pragma unroll
        for (int c = 0; c < 4; c++)
            if (best2[c]) atomicMax(&redB[tc * 4 + c], best2[c]);
    }
    __syncthreads();
    if (tid < BT) {
        if (redA[tid]) atomicMax(&g_best[row0 + tid], redA[tid]);
    } else if (tid < 2 * BT && !diag) {
        int q = tid - BT;
        if (redB[q]) atomicMax(&g_best[col0 + q], redB[q]);
    }
}

// ---------------- positives: warp-per-anchor over class member list ---------
__global__ void pos_sample_k(const int* __restrict__ labels,
                             uint32_t kp0, uint32_t kp1) {
    const int t = threadIdx.x;
    const int anchor = (blockIdx.x * 256 + t) >> 5;
    const int lane = t & 31;
    const int li = labels[anchor];
    const int cnt = min(g_ccnt[li], MAXMEM);
    u64 best = 0ull;
    for (int s = lane; s < cnt; s += 32) {
        int j = g_members[li * MAXMEM + s];
        if (j != anchor) {
            uint32_t bits = jax_bits32(kp0, kp1, (uint32_t)(anchor * NB + j));
            u64 p = pack_vi(jax_gumbel(bits), j);
            if (p > best) best = p;
        }
    }
#pragma unroll
    for (int o = 16; o; o >>= 1) {
        u64 q = __shfl_xor_sync(0xFFFFFFFFu, best, o);
        if (q > best) best = q;
    }
    if (lane == 0)
        g_posidx[anchor] = (int)(0xFFFFFFFFu - (uint32_t)best);
}

// ---------------- finalize + reduce ------------------------------------------
__global__ void finalize_k(const float* __restrict__ emb,
                           const int* __restrict__ labels,
                           const float* __restrict__ beta) {
    int w = (blockIdx.x * blockDim.x + threadIdx.x) >> 5;
    int lane = threadIdx.x & 31;
    if (w >= NB) return;
    int pi = g_posidx[w];
    int ni = (int)(0xFFFFFFFFu - (uint32_t)g_best[w]);
    float4 a = *(const float4*)(emb + w * NDIM + lane * 4);
    float4 p = *(const float4*)(emb + pi * NDIM + lane * 4);
    float4 n = *(const float4*)(emb + ni * NDIM + lane * 4);
    float dx, sap, san;
    dx = a.x - p.x; sap = dx * dx; dx = a.y - p.y; sap += dx * dx;
    dx = a.z - p.z; sap += dx * dx; dx = a.w - p.w; sap += dx * dx;
    dx = a.x - n.x; san = dx * dx; dx = a.y - n.y; san += dx * dx;
    dx = a.z - n.z; san += dx * dx; dx = a.w - n.w; san += dx * dx;
#pragma unroll
    for (int o = 16; o; o >>= 1) {
        sap += __shfl_xor_sync(0xFFFFFFFFu, sap, o);
        san += __shfl_xor_sync(0xFFFFFFFFu, san, o);
    }
    if (lane == 0) {
        float d_ap = sqrtf(sap + 1e-8f);
        float d_an = sqrtf(san + 1e-8f);
        float ba = beta[labels[w]];
        float pl = fmaxf(d_ap - ba + 0.2f, 0.0f);
        float nl = fmaxf(ba - d_an + 0.2f, 0.0f);
        g_loss[w] = pl + nl;
        g_cnt[w]  = (pl > 0.0f ? 1.0f : 0.0f) + (nl > 0.0f ? 1.0f : 0.0f);
    }
}

__global__ void reduce_k(float* __restrict__ out) {
    __shared__ float st[256], sc[256];
    int t = threadIdx.x;
    float s = 0.f, c = 0.f;
    for (int i = t; i < NB; i += 256) { s += g_loss[i]; c += g_cnt[i]; }
    st[t] = s; sc[t] = c;
    __syncthreads();
    for (int o = 128; o; o >>= 1) {
        if (t < o) { st[t] += st[t + o]; sc[t] += sc[t + o]; }
        __syncthreads();
    }
    if (t == 0) out[0] = (sc[0] == 0.0f) ? st[0] : st[0] / sc[0];
}

// ---------------- host -------------------------------------------------------
extern "C" void kernel_launch(void* const* d_in, const int* in_sizes, int n_in,
                              void* d_out, int out_size) {
    const float* emb    = (const float*)d_in[0];
    const int*   labels = (const int*)d_in[1];
    const float* beta   = (const float*)d_in[2];
    float* out = (float*)d_out;

    uint32_t kn0, kn1, kp0, kp1;
    tf2x32(0u, 42u, 0u, 0u, kn0, kn1);   // foldlike split: k_neg
    tf2x32(0u, 42u, 0u, 1u, kp0, kp1);   // k_pos

    convert_k<<<NB * NDIM / 4 / 256, 256>>>(emb);
    norm_k<<<NB * 32 / 256, 256>>>(emb);
    bin_k<<<NB / 256, 256>>>(labels);
    gemm_k<<<NGPAIRS, 256>>>();
    neg_sample_k<<<NPAIRS, NTHREADS>>>(labels, kn0, kn1);
    pos_sample_k<<<NB / 8, 256>>>(labels, kp0, kp1);
    finalize_k<<<NB * 32 / 256, 256>>>(emb, labels, beta);
    reduce_k<<<1, 256>>>(out);
}

// round 17
// speedup vs baseline: 1.1783x; 1.1096x over previous
#include <cuda_runtime.h>
#include <cuda_bf16.h>
#include <cstdint>
#include <cfloat>

#define NB      4096
#define NDIM    128
// GEMM tiles (tensor core, mma.sync)
#define GT      128
#define NGT     (NB / GT)                 // 32
#define NGPAIRS (NGT * (NGT + 1) / 2)     // 528
#define SPAD    20                        // padded smem row stride (words)
// sampling tiles
#define BT      64
#define NRT     (NB / BT)                 // 64
#define NPAIRS  (NRT * (NRT + 1) / 2)     // 2080
#define NTHREADS 256
#define NCLASS  100
#define MAXMEM  64

typedef unsigned long long u64;

// ---------------- device scratch (static, no allocation) --------------------
__device__ __nv_bfloat16 g_embH[NB * NDIM];
__device__ __nv_bfloat16 g_embL[NB * NDIM];
__device__ float g_dot[(size_t)NB * NB];     // 64MB; upper 128-tiles written
__device__ float g_sqnorm[NB];
__device__ u64   g_best[NB];
__device__ int   g_posidx[NB];
__device__ float g_loss[NB];
__device__ float g_cnt[NB];
__device__ int   g_ccnt[NCLASS];
__device__ int   g_members[NCLASS * MAXMEM];

// ---------------- mma.sync m16n8k16 bf16 (sm_80+, compiles on compute_100) --
__device__ __forceinline__ void mma_bf16(float* c, const uint32_t* a,
                                         const uint32_t* b) {
    asm volatile(
        "mma.sync.aligned.m16n8k16.row.col.f32.bf16.bf16.f32 "
        "{%0,%1,%2,%3}, {%4,%5,%6,%7}, {%8,%9}, {%0,%1,%2,%3};"
        : "+f"(c[0]), "+f"(c[1]), "+f"(c[2]), "+f"(c[3])
        : "r"(a[0]), "r"(a[1]), "r"(a[2]), "r"(a[3]),
          "r"(b[0]), "r"(b[1]));
}

// ---------------- threefry2x32 ----------------------------------------------
__host__ __device__ __forceinline__ void tf2x32(uint32_t k0, uint32_t k1,
                                                uint32_t c0, uint32_t c1,
                                                uint32_t& o0, uint32_t& o1) {
    const uint32_t ks2 = k0 ^ k1 ^ 0x1BD11BDAu;
    uint32_t x0 = c0 + k0;
    uint32_t x1 = c1 + k1;
#define TFR(r) { x0 += x1; x1 = (x1 << r) | (x1 >> (32 - r)); x1 ^= x0; }
    TFR(13) TFR(15) TFR(26) TFR(6)   x0 += k1;  x1 += ks2 + 1u;
    TFR(17) TFR(29) TFR(16) TFR(24)  x0 += ks2; x1 += k0  + 2u;
    TFR(13) TFR(15) TFR(26) TFR(6)   x0 += k0;  x1 += k1  + 3u;
    TFR(17) TFR(29) TFR(16) TFR(24)  x0 += k1;  x1 += ks2 + 4u;
    TFR(13) TFR(15) TFR(26) TFR(6)   x0 += ks2; x1 += k0  + 5u;
#undef TFR
    o0 = x0; o1 = x1;
}
__device__ __forceinline__ uint32_t jax_bits32(uint32_t k0, uint32_t k1, uint32_t n) {
    uint32_t o0, o1;
    tf2x32(k0, k1, 0u, n, o0, o1);
    return o0 ^ o1;
}
__device__ __forceinline__ float jax_gumbel(uint32_t bits) {
    float f = __uint_as_float((bits >> 9) | 0x3f800000u) - 1.0f;
    float u = fmaxf(f, 1.17549435e-38f);
    float nl = -logf(u);               // accurate: u->1 tail decides winners
    return -__logf(nl);
}
__device__ __forceinline__ u64 pack_vi(float v, int idx) {
    uint32_t s = __float_as_uint(v);
    s = (s & 0x80000000u) ? ~s : (s | 0x80000000u);
    return ((u64)s << 32) | (uint32_t)(0xFFFFFFFFu - (uint32_t)idx);
}

// ---------------- prep: fp32 -> bf16 hi/lo split -----------------------------
__global__ void convert_k(const float* __restrict__ emb) {
    int idx = blockIdx.x * blockDim.x + threadIdx.x;   // float4 units
    float4 v = ((const float4*)emb)[idx];
    __nv_bfloat16 h0 = __float2bfloat16(v.x), h1 = __float2bfloat16(v.y);
    __nv_bfloat16 h2 = __float2bfloat16(v.z), h3 = __float2bfloat16(v.w);
    __nv_bfloat16 l0 = __float2bfloat16(v.x - __bfloat162float(h0));
    __nv_bfloat16 l1 = __float2bfloat16(v.y - __bfloat162float(h1));
    __nv_bfloat16 l2 = __float2bfloat16(v.z - __bfloat162float(h2));
    __nv_bfloat16 l3 = __float2bfloat16(v.w - __bfloat162float(h3));
    __nv_bfloat162 ph0; ph0.x = h0; ph0.y = h1;
    __nv_bfloat162 ph1; ph1.x = h2; ph1.y = h3;
    __nv_bfloat162 pl0; pl0.x = l0; pl0.y = l1;
    __nv_bfloat162 pl1; pl1.x = l2; pl1.y = l3;
    ((__nv_bfloat162*)g_embH)[idx * 2]     = ph0;
    ((__nv_bfloat162*)g_embH)[idx * 2 + 1] = ph1;
    ((__nv_bfloat162*)g_embL)[idx * 2]     = pl0;
    ((__nv_bfloat162*)g_embL)[idx * 2 + 1] = pl1;
}

__global__ void norm_k(const float* __restrict__ emb) {
    int gid = blockIdx.x * blockDim.x + threadIdx.x;
    if (gid < NCLASS) g_ccnt[gid] = 0;
    int w = gid >> 5;
    int lane = threadIdx.x & 31;
    if (w >= NB) return;
    float4 v = *(const float4*)(emb + w * NDIM + lane * 4);
    float s = v.x * v.x + v.y * v.y + v.z * v.z + v.w * v.w;
#pragma unroll
    for (int o = 16; o; o >>= 1) s += __shfl_xor_sync(0xFFFFFFFFu, s, o);
    if (lane == 0) { g_sqnorm[w] = s; g_best[w] = 0ull; }
}

__global__ void bin_k(const int* __restrict__ labels) {
    int i = blockIdx.x * blockDim.x + threadIdx.x;
    if (i >= NB) return;
    int c = labels[i];
    int s = atomicAdd(&g_ccnt[c], 1);
    if (s < MAXMEM) g_members[c * MAXMEM + s] = i;
}

// ---------------- tensor-core Gram: smem-staged, conflict-free stride -------
// Fragment map (m16n8k16, row.col), verified rel_err=0 in rounds 13-16.
// Row stride SPAD=20 words: frag-load bank = (20g + o + tig) % 32, all 32
// lanes distinct -> conflict-free LDS.
__global__ void __launch_bounds__(256, 2)
gemm_k() {
    __shared__ uint32_t sAH[GT * SPAD], sAL[GT * SPAD];   // 128 rows x 16 words
    __shared__ uint32_t sBH[GT * SPAD], sBL[GT * SPAD];

    const int tid = threadIdx.x;
    const int w = tid >> 5;
    const int lane = tid & 31;
    const int g = lane >> 2, tig = lane & 3;

    // decode triangular pair over 128-tiles
    int bid = blockIdx.x;
    int I = (int)((2.0f * NGT + 1.0f
                   - sqrtf((2.0f * NGT + 1.0f) * (2.0f * NGT + 1.0f)
                           - 8.0f * (float)bid)) * 0.5f);
    while (I * (2 * NGT + 1 - I) / 2 > bid) I--;
    while ((I + 1) * (2 * NGT - I) / 2 <= bid) I++;
    const int J = I + (bid - I * (2 * NGT + 1 - I) / 2);
    const int row0 = I * GT;
    const int col0 = J * GT;

    const uint32_t* H = (const uint32_t*)g_embH;   // 64 words per row
    const uint32_t* L = (const uint32_t*)g_embL;
    const int arow = w * 16 + g;                   // local A row

    float acc[16][4];
#pragma unroll
    for (int s = 0; s < 16; s++)
#pragma unroll
        for (int q = 0; q < 4; q++) acc[s][q] = 0.f;

    for (int kc = 0; kc < 8; kc++) {               // 16-bf16 chunks
        const int wb = kc * 8;
        __syncthreads();
        for (int idx = tid; idx < GT * 8; idx += 256) {
            int row = idx >> 3, wc = idx & 7;
            int so = row * SPAD + wc;
            sAH[so] = H[(size_t)(row0 + row) * 64 + wb + wc];
            sAL[so] = L[(size_t)(row0 + row) * 64 + wb + wc];
            sBH[so] = H[(size_t)(col0 + row) * 64 + wb + wc];
            sBL[so] = L[(size_t)(col0 + row) * 64 + wb + wc];
        }
        __syncthreads();

        uint32_t ah[4], al[4];
        ah[0] = sAH[arow * SPAD + tig];
        ah[1] = sAH[(arow + 8) * SPAD + tig];
        ah[2] = sAH[arow * SPAD + tig + 4];
        ah[3] = sAH[(arow + 8) * SPAD + tig + 4];
        al[0] = sAL[arow * SPAD + tig];
        al[1] = sAL[(arow + 8) * SPAD + tig];
        al[2] = sAL[arow * SPAD + tig + 4];
        al[3] = sAL[(arow + 8) * SPAD + tig + 4];

#pragma unroll
        for (int s = 0; s < 16; s++) {
            const int brow = s * 8 + g;
            uint32_t bh[2] = {sBH[brow * SPAD + tig], sBH[brow * SPAD + tig + 4]};
            uint32_t bl[2] = {sBL[brow * SPAD + tig], sBL[brow * SPAD + tig + 4]};
            mma_bf16(acc[s], ah, bh);   // hi*hi
            mma_bf16(acc[s], ah, bl);   // hi*lo
            mma_bf16(acc[s], al, bh);   // lo*hi  (lo*lo dropped: <=4e-6)
        }
    }

    const int mrow = row0 + arow;
#pragma unroll
    for (int s = 0; s < 16; s++) {
        const int col = col0 + s * 8 + tig * 2;
        float2 lo; lo.x = acc[s][0]; lo.y = acc[s][1];
        float2 hi; hi.x = acc[s][2]; hi.y = acc[s][3];
        *(float2*)&g_dot[(size_t)mrow * NB + col] = lo;
        *(float2*)&g_dot[(size_t)(mrow + 8) * NB + col] = hi;
    }
}

// ---------------- negatives: epilogue-only over precomputed dots ------------
__global__ void __launch_bounds__(NTHREADS, 5)
neg_sample_k(const int* __restrict__ labels, uint32_t kn0, uint32_t kn1) {
    __shared__ int labA[BT], labB[BT];
    __shared__ float sqA[BT], sqB[BT];
    __shared__ u64 redA[BT], redB[BT];

    const int tid = threadIdx.x;
    const int tr = tid >> 4;
    const int tc = tid & 15;

    int bid = blockIdx.x;
    int I = (int)((2.0f * NRT + 1.0f
                   - sqrtf((2.0f * NRT + 1.0f) * (2.0f * NRT + 1.0f)
                           - 8.0f * (float)bid)) * 0.5f);
    while (I * (2 * NRT + 1 - I) / 2 > bid) I--;
    while ((I + 1) * (2 * NRT - I) / 2 <= bid) I++;
    const int J = I + (bid - I * (2 * NRT + 1 - I) / 2);
    const int row0 = I * BT;
    const int col0 = J * BT;
    const bool diag = (I == J);

    if (tid < BT) {
        labA[tid] = labels[row0 + tid]; sqA[tid] = g_sqnorm[row0 + tid];
        redA[tid] = 0ull;
    } else if (tid < 2 * BT) {
        int q = tid - BT;
        labB[q] = labels[col0 + q]; sqB[q] = g_sqnorm[col0 + q];
        redB[q] = 0ull;
    }
    __syncthreads();

    float acc[4][4];
#pragma unroll
    for (int r = 0; r < 4; r++) {
        float4 v = *(const float4*)&g_dot[(size_t)(row0 + tr * 4 + r) * NB
                                          + col0 + tc * 4];
        acc[r][0] = v.x; acc[r][1] = v.y; acc[r][2] = v.z; acc[r][3] = v.w;
    }

    float sqr[4]; int labr[4];
#pragma unroll
    for (int r = 0; r < 4; r++) {
        sqr[r]  = sqA[tr * 4 + r];
        labr[r] = labA[tr * 4 + r];
    }

    u64 best1[4] = {0ull, 0ull, 0ull, 0ull};
    u64 best2[4] = {0ull, 0ull, 0ull, 0ull};

#pragma unroll
    for (int cc = 0; cc < 4; cc++) {
        const int cl = tc * 4 + cc;
        const int j  = col0 + cl;
        const int labj = labB[cl];
        const float sqj = sqB[cl];
#pragma unroll
        for (int r = 0; r < 4; r++) {
            if (labr[r] == labj) continue;      // same-label -> -inf logit
            const int i = row0 + tr * 4 + r;
            float d2 = (sqr[r] + sqj) - 2.0f * acc[r][cc];
            d2 = fmaxf(d2, 0.25f);              // == clip d at 0.5
            d2 = fminf(d2, 3.999f);             // guard log(<=0)
            float lq = -63.0f * __logf(d2)
                       - 62.5f * __logf(fmaf(-0.25f, d2, 1.0f));
            {   // orientation 1: anchor i, candidate j
                uint32_t bits = jax_bits32(kn0, kn1, (uint32_t)(i * NB + j));
                u64 p = pack_vi(lq + jax_gumbel(bits), j);
                if (p > best1[r]) best1[r] = p;
            }
            if (!diag) {  // orientation 2: anchor j, candidate i
                uint32_t bits = jax_bits32(kn0, kn1, (uint32_t)(j * NB + i));
                u64 p = pack_vi(lq + jax_gumbel(bits), i);
                if (p > best2[cc]) best2[cc] = p;
            }
        }
    }

#pragma unroll
    for (int r = 0; r < 4; r++)
        if (best1[r]) atomicMax(&redA[tr * 4 + r], best1[r]);
    if (!diag) {
#pragma unroll
        for (int c = 0; c < 4; c++)
            if (best2[c]) atomicMax(&redB[tc * 4 + c], best2[c]);
    }
    __syncthreads();
    if (tid < BT) {
        if (redA[tid]) atomicMax(&g_best[row0 + tid], redA[tid]);
    } else if (tid < 2 * BT && !diag) {
        int q = tid - BT;
        if (redB[q]) atomicMax(&g_best[col0 + q], redB[q]);
    }
}

// ---------------- positives: warp-per-anchor over class member list ---------
__global__ void pos_sample_k(const int* __restrict__ labels,
                             uint32_t kp0, uint32_t kp1) {
    const int t = threadIdx.x;
    const int anchor = (blockIdx.x * 256 + t) >> 5;
    const int lane = t & 31;
    const int li = labels[anchor];
    const int cnt = min(g_ccnt[li], MAXMEM);
    u64 best = 0ull;
    for (int s = lane; s < cnt; s += 32) {
        int j = g_members[li * MAXMEM + s];
        if (j != anchor) {
            uint32_t bits = jax_bits32(kp0, kp1, (uint32_t)(anchor * NB + j));
            u64 p = pack_vi(jax_gumbel(bits), j);
            if (p > best) best = p;
        }
    }
#pragma unroll
    for (int o = 16; o; o >>= 1) {
        u64 q = __shfl_xor_sync(0xFFFFFFFFu, best, o);
        if (q > best) best = q;
    }
    if (lane == 0)
        g_posidx[anchor] = (int)(0xFFFFFFFFu - (uint32_t)best);
}

// ---------------- finalize + reduce ------------------------------------------
__global__ void finalize_k(const float* __restrict__ emb,
                           const int* __restrict__ labels,
                           const float* __restrict__ beta) {
    int w = (blockIdx.x * blockDim.x + threadIdx.x) >> 5;
    int lane = threadIdx.x & 31;
    if (w >= NB) return;
    int pi = g_posidx[w];
    int ni = (int)(0xFFFFFFFFu - (uint32_t)g_best[w]);
    float4 a = *(const float4*)(emb + w * NDIM + lane * 4);
    float4 p = *(const float4*)(emb + pi * NDIM + lane * 4);
    float4 n = *(const float4*)(emb + ni * NDIM + lane * 4);
    float dx, sap, san;
    dx = a.x - p.x; sap = dx * dx; dx = a.y - p.y; sap += dx * dx;
    dx = a.z - p.z; sap += dx * dx; dx = a.w - p.w; sap += dx * dx;
    dx = a.x - n.x; san = dx * dx; dx = a.y - n.y; san += dx * dx;
    dx = a.z - n.z; san += dx * dx; dx = a.w - n.w; san += dx * dx;
#pragma unroll
    for (int o = 16; o; o >>= 1) {
        sap += __shfl_xor_sync(0xFFFFFFFFu, sap, o);
        san += __shfl_xor_sync(0xFFFFFFFFu, san, o);
    }
    if (lane == 0) {
        float d_ap = sqrtf(sap + 1e-8f);
        float d_an = sqrtf(san + 1e-8f);
        float ba = beta[labels[w]];
        float pl = fmaxf(d_ap - ba + 0.2f, 0.0f);
        float nl = fmaxf(ba - d_an + 0.2f, 0.0f);
        g_loss[w] = pl + nl;
        g_cnt[w]  = (pl > 0.0f ? 1.0f : 0.0f) + (nl > 0.0f ? 1.0f : 0.0f);
    }
}

__global__ void reduce_k(float* __restrict__ out) {
    __shared__ float st[256], sc[256];
    int t = threadIdx.x;
    float s = 0.f, c = 0.f;
    for (int i = t; i < NB; i += 256) { s += g_loss[i]; c += g_cnt[i]; }
    st[t] = s; sc[t] = c;
    __syncthreads();
    for (int o = 128; o; o >>= 1) {
        if (t < o) { st[t] += st[t + o]; sc[t] += sc[t + o]; }
        __syncthreads();
    }
    if (t == 0) out[0] = (sc[0] == 0.0f) ? st[0] : st[0] / sc[0];
}

// ---------------- host -------------------------------------------------------
extern "C" void kernel_launch(void* const* d_in, const int* in_sizes, int n_in,
                              void* d_out, int out_size) {
    const float* emb    = (const float*)d_in[0];
    const int*   labels = (const int*)d_in[1];
    const float* beta   = (const float*)d_in[2];
    float* out = (float*)d_out;

    uint32_t kn0, kn1, kp0, kp1;
    tf2x32(0u, 42u, 0u, 0u, kn0, kn1);   // foldlike split: k_neg
    tf2x32(0u, 42u, 0u, 1u, kp0, kp1);   // k_pos

    convert_k<<<NB * NDIM / 4 / 256, 256>>>(emb);
    norm_k<<<NB * 32 / 256, 256>>>(emb);
    bin_k<<<NB / 256, 256>>>(labels);
    gemm_k<<<NGPAIRS, 256>>>();
    neg_sample_k<<<NPAIRS, NTHREADS>>>(labels, kn0, kn1);
    pos_sample_k<<<NB / 8, 256>>>(labels, kp0, kp1);
    finalize_k<<<NB * 32 / 256, 256>>>(emb, labels, beta);
    reduce_k<<<1, 256>>>(out);
}